// round 14
// baseline (speedup 1.0000x reference)
#include <cuda_runtime.h>
#include <cstdint>
#include <cstddef>

// Problem constants
#define B_   4
#define C_   192
#define H_   128
#define W_   128
#define P_   16384
#define ND   3
#define C2   64
#define NH   2
#define HD   32
#define MQKV 576
#define SCALE 0.17677669529663687f   // 32^-0.5

// Scratch (alloc-free: __device__ globals)
__device__ float g_x  [(size_t)B_*C_*P_];     // tf32-rounded, qkv-gemm input
__device__ float g_qkv[(size_t)B_*MQKV*P_];   // fp32, attention input
__device__ float g_xo [(size_t)B_*C_*P_];     // tf32-rounded, proj-gemm input
__device__ float g_wq [(size_t)MQKV*C_];      // qkv_w: rounded + pair-permuted
__device__ float g_wp [(size_t)C_*C_];        // proj_w: rounded + pair-permuted

__device__ __forceinline__ float f2tf(float f) {
    uint32_t u;
    asm("cvt.rna.tf32.f32 %0, %1;" : "=r"(u) : "f"(f));
    return __uint_as_float(u);
}

// ---------------------------------------------------------------------------
// Stage 0: weight prep — round to tf32 and pair-permute (k,k+4) per kstep-of-8
// ---------------------------------------------------------------------------
__global__ __launch_bounds__(256) void prep_w(
    const float* __restrict__ qkv_w, const float* __restrict__ proj_w)
{
    int i = blockIdx.x * 256 + threadIdx.x;
    if (i < MQKV * C_) {
        int m = i / C_, k = i - m * C_;
        int dc = (k >> 3) * 8 + 2 * (k & 3) + ((k >> 2) & 1);
        g_wq[(size_t)m * C_ + dc] = f2tf(qkv_w[i]);
    }
    if (i < C_ * C_) {
        int m = i / C_, k = i - m * C_;
        int dc = (k >> 3) * 8 + 2 * (k & 3) + ((k >> 2) & 1);
        g_wp[(size_t)m * C_ + dc] = f2tf(proj_w[i]);
    }
}

// ---------------------------------------------------------------------------
// Stage 1: depthwise 3x3 conv (zero pad) + residual + bias; output tf32-rounded
// ---------------------------------------------------------------------------
__global__ __launch_bounds__(256) void pos_kernel(
    const float* __restrict__ x, const float* __restrict__ pw,
    const float* __restrict__ pb)
{
    int idx = blockIdx.x * 256 + threadIdx.x;
    if (idx >= B_*C_*P_) return;
    int pix = idx & (P_-1);
    int bc  = idx >> 14;
    int c   = bc % C_;
    int y  = pix >> 7;
    int xx = pix & 127;
    const float* xb = x + (size_t)bc * P_;
    const float* w  = pw + c * 9;
    float s = x[idx];
    #pragma unroll
    for (int kh = 0; kh < 3; kh++) {
        int yy = y + kh - 1;
        if (yy < 0 || yy >= H_) continue;
        #pragma unroll
        for (int kw = 0; kw < 3; kw++) {
            int xc = xx + kw - 1;
            if (xc < 0 || xc >= W_) continue;
            s += xb[yy * W_ + xc] * w[kh * 3 + kw];
        }
    }
    g_x[idx] = f2tf(s + pb[c]);
}

// ---------------------------------------------------------------------------
// tf32 mma.sync GEMM with cp.async 4-stage pipeline.
// CTA tile 64(m) x 128(n) x 16(k); 8 warps (2m x 4n); warp tile 32x32.
// Inputs pre-rounded/permuted -> staging = pure 16B async copies.
// Ring: wait_group 2 -> sync -> issue t+3 -> commit -> compute t.
// Dynamic smem 58 KB -> 3 CTAs/SM.
// ---------------------------------------------------------------------------
#define GBM 64
#define GBN 128
#define GK  192
#define BKT 16
#define NKT 12
#define NSTG 4
#define AP  24
#define BNP 136
#define AS_WORDS (GBM * AP)        // 1536
#define BS_WORDS (BKT * BNP)       // 2176
#define AS_BYTES (AS_WORDS * 4)
#define BS_BYTES (BS_WORDS * 4)
#define GEMM_DYN ((NSTG * (AS_WORDS + BS_WORDS)) * 4)   // 59392

#define CP16(dst_u32, src) \
    asm volatile("cp.async.cg.shared.global [%0], [%1], 16;" \
                 :: "r"(dst_u32), "l"(src) : "memory")
#define CP_COMMIT() asm volatile("cp.async.commit_group;" ::: "memory")
#define CP_WAIT2()  asm volatile("cp.async.wait_group 2;" ::: "memory")

__device__ __forceinline__ void mma_tf32(float (&d)[4], const uint32_t (&a)[4],
                                         const uint32_t (&b)[2]) {
    asm volatile(
        "mma.sync.aligned.m16n8k8.row.col.f32.tf32.tf32.f32 "
        "{%0,%1,%2,%3}, {%4,%5,%6,%7}, {%8,%9}, {%0,%1,%2,%3};"
        : "+f"(d[0]), "+f"(d[1]), "+f"(d[2]), "+f"(d[3])
        : "r"(a[0]), "r"(a[1]), "r"(a[2]), "r"(a[3]), "r"(b[0]), "r"(b[1]));
}

__global__ __launch_bounds__(256, 3) void gemm_mma(
    const float* __restrict__ Wp, const float* __restrict__ X,
    float* __restrict__ Y, int Mtot)
{
    extern __shared__ float dsm[];
    float* AsB = dsm;                         // NSTG x AS_WORDS
    float* BsB = dsm + NSTG * AS_WORDS;       // NSTG x BS_WORDS
    uint32_t as_u = (uint32_t)__cvta_generic_to_shared(AsB);
    uint32_t bs_u = (uint32_t)__cvta_generic_to_shared(BsB);

    int tid  = threadIdx.x;
    int lane = tid & 31;
    int wid  = tid >> 5;
    int wm   = wid & 1;
    int wn   = wid >> 1;
    int n0   = blockIdx.x * GBN;
    int m0   = blockIdx.y * GBM;
    int b    = blockIdx.z;
    const float* Xb = X + (size_t)b * C_ * P_;
    float* Yb = Y + (size_t)b * Mtot * P_;

    int lr = lane >> 2;
    int lc = lane & 3;

    // A staging: 1 x 16B/thread/stage (pure copy of pre-permuted W)
    int arow = tid >> 2;
    int a4   = (tid & 3) << 2;
    const float* aptr = Wp + (size_t)(m0 + arow) * GK + a4;
    uint32_t a_dst = as_u + (uint32_t)(arow * AP + a4) * 4;
    // B staging: 2 x 16B/thread/stage
    int brow0 = tid >> 5;
    int brow1 = brow0 + 8;
    int bc4   = (tid & 31) << 2;
    const float* bptr0 = Xb + (size_t)brow0 * P_ + n0 + bc4;
    const float* bptr1 = Xb + (size_t)brow1 * P_ + n0 + bc4;
    uint32_t b_dst0 = bs_u + (uint32_t)(brow0 * BNP + bc4) * 4;
    uint32_t b_dst1 = bs_u + (uint32_t)(brow1 * BNP + bc4) * 4;

    // Prologue: issue stages 0..2
    #pragma unroll
    for (int s = 0; s < NSTG - 1; s++) {
        int k0 = s * BKT;
        CP16(a_dst  + s * AS_BYTES, aptr + k0);
        CP16(b_dst0 + s * BS_BYTES, bptr0 + (size_t)k0 * P_);
        CP16(b_dst1 + s * BS_BYTES, bptr1 + (size_t)k0 * P_);
        CP_COMMIT();
    }

    float acc[2][4][4];
    #pragma unroll
    for (int mt = 0; mt < 2; mt++)
        #pragma unroll
        for (int nt = 0; nt < 4; nt++)
            #pragma unroll
            for (int r = 0; r < 4; r++) acc[mt][nt][r] = 0.f;

    for (int t = 0; t < NKT; t++) {
        CP_WAIT2();            // stage t complete (this thread's groups)
        __syncthreads();       // all threads: stage t visible; compute t-1 done

        if (t + NSTG - 1 < NKT) {
            int s  = (t + NSTG - 1) & (NSTG - 1);
            int k0 = (t + NSTG - 1) * BKT;
            CP16(a_dst  + s * AS_BYTES, aptr + k0);
            CP16(b_dst0 + s * BS_BYTES, bptr0 + (size_t)k0 * P_);
            CP16(b_dst1 + s * BS_BYTES, bptr1 + (size_t)k0 * P_);
        }
        CP_COMMIT();           // commit every iter (empty groups keep count aligned)

        const float* Asb = AsB + (t & (NSTG - 1)) * AS_WORDS;
        const uint32_t* Bsu = reinterpret_cast<const uint32_t*>(
            BsB + (t & (NSTG - 1)) * BS_WORDS);

        #pragma unroll
        for (int s = 0; s < 2; s++) {
            uint32_t a[2][4], bf[4][2];
            #pragma unroll
            for (int mt = 0; mt < 2; mt++) {
                int r = wm * 32 + mt * 16 + lr;
                uint2 u0 = *reinterpret_cast<const uint2*>(Asb + r * AP + s * 8 + 2 * lc);
                uint2 u1 = *reinterpret_cast<const uint2*>(Asb + (r + 8) * AP + s * 8 + 2 * lc);
                a[mt][0] = u0.x; a[mt][2] = u0.y;
                a[mt][1] = u1.x; a[mt][3] = u1.y;
            }
            #pragma unroll
            for (int nt = 0; nt < 4; nt++) {
                int c0 = (s * 8 + lc) * BNP + wn * 32 + nt * 8 + lr;
                bf[nt][0] = Bsu[c0];
                bf[nt][1] = Bsu[c0 + 4 * BNP];
            }
            #pragma unroll
            for (int mt = 0; mt < 2; mt++)
                #pragma unroll
                for (int nt = 0; nt < 4; nt++)
                    mma_tf32(acc[mt][nt], a[mt], bf[nt]);
        }
    }

    #pragma unroll
    for (int mt = 0; mt < 2; mt++)
        #pragma unroll
        for (int nt = 0; nt < 4; nt++) {
            int r = m0 + wm * 32 + mt * 16 + lr;
            int c = n0 + wn * 32 + nt * 8 + lc * 2;
            float2 v0 = { acc[mt][nt][0], acc[mt][nt][1] };
            float2 v1 = { acc[mt][nt][2], acc[mt][nt][3] };
            *reinterpret_cast<float2*>(Yb + (size_t)r * P_ + c)       = v0;
            *reinterpret_cast<float2*>(Yb + (size_t)(r + 8) * P_ + c) = v1;
        }
}

// ---------------------------------------------------------------------------
// Stage 3: attention via SMEM row-staging (unchanged from R13).
// ---------------------------------------------------------------------------
#define HHD 16
#define KV_WORDS (HD * 3 * W_)          // 12288 floats (48 KB)
#define ATT_SMEM ((KV_WORDS + 2 * W_ * 9) * 4)   // 58368 B

__device__ __forceinline__ int reflect_i(int t, int n) {
    return t < 0 ? -t : (t >= n ? 2*n - 2 - t : t);
}

__global__ __launch_bounds__(256) void attn_kernel()
{
    extern __shared__ float asm_[];
    float* kv  = asm_;                 // [32 ch][3 rows][128 x]
    float* ssc = asm_ + KV_WORDS;      // [2][128*9]

    int tid  = threadIdx.x;
    int half = tid >> 7;
    int px   = tid & 127;
    int y    = blockIdx.x;
    int head = blockIdx.y & 1;
    int dil  = blockIdx.y >> 1;
    int b    = blockIdx.z;
    int dl   = dil + 1;
    int p    = y * W_ + px;

    int xs[3];
    #pragma unroll
    for (int jx = 0; jx < 3; jx++)
        xs[jx] = reflect_i(px + (jx - 1) * dl, W_);
    int ys[3];
    #pragma unroll
    for (int jy = 0; jy < 3; jy++)
        ys[jy] = reflect_i(y + (jy - 1) * dl, H_);

    size_t chan0 = (size_t)b * MQKV + dil * C2 + head * HD;
    const float* qp = g_qkv + (chan0 + (size_t)half * HHD) * P_;
    const float* kp = g_qkv + (chan0 + (size_t)C_)   * P_;
    const float* vp = g_qkv + (chan0 + (size_t)2*C_) * P_;

    #pragma unroll
    for (int i = 0; i < 12; i++) {
        int u    = tid + i * 256;
        int pair = u >> 5;
        int x4   = (u & 31) << 2;
        int ch   = pair / 3;
        int jy   = pair - ch * 3;
        float4 v = *reinterpret_cast<const float4*>(
            kp + (size_t)ch * P_ + ys[jy] * W_ + x4);
        *reinterpret_cast<float4*>(kv + pair * W_ + x4) = v;
    }
    __syncthreads();

    float sc[9];
    #pragma unroll
    for (int j = 0; j < 9; j++) sc[j] = 0.f;

    #pragma unroll 4
    for (int d = 0; d < HHD; d++) {
        float qd = qp[(size_t)d * P_ + p];
        const float* kb = kv + (half * HHD + d) * 3 * W_;
        #pragma unroll
        for (int jy = 0; jy < 3; jy++) {
            const float* kr = kb + jy * W_;
            #pragma unroll
            for (int jx = 0; jx < 3; jx++)
                sc[jy*3 + jx] += qd * kr[xs[jx]];
        }
    }

    {
        float* mine = &ssc[half * (W_ * 9) + px * 9];
        #pragma unroll
        for (int j = 0; j < 9; j++) mine[j] = sc[j];
    }
    __syncthreads();
    {
        const float* other = &ssc[(half ^ 1) * (W_ * 9) + px * 9];
        #pragma unroll
        for (int j = 0; j < 9; j++) sc[j] += other[j];
    }

    float mx = sc[0] * SCALE;
    #pragma unroll
    for (int j = 0; j < 9; j++) { sc[j] *= SCALE; mx = fmaxf(mx, sc[j]); }
    float sum = 0.f;
    #pragma unroll
    for (int j = 0; j < 9; j++) { sc[j] = __expf(sc[j] - mx); sum += sc[j]; }
    float inv = 1.f / sum;

    #pragma unroll
    for (int i = 0; i < 12; i++) {
        int u    = tid + i * 256;
        int pair = u >> 5;
        int x4   = (u & 31) << 2;
        int ch   = pair / 3;
        int jy   = pair - ch * 3;
        float4 v = *reinterpret_cast<const float4*>(
            vp + (size_t)ch * P_ + ys[jy] * W_ + x4);
        *reinterpret_cast<float4*>(kv + pair * W_ + x4) = v;
    }
    __syncthreads();

    float* op = g_xo + ((size_t)b * C_ + dil * C2 + head * HD
                        + (size_t)half * HHD) * P_ + p;
    #pragma unroll 4
    for (int d = 0; d < HHD; d++) {
        const float* vb = kv + (half * HHD + d) * 3 * W_;
        float a = 0.f;
        #pragma unroll
        for (int jy = 0; jy < 3; jy++) {
            const float* vr = vb + jy * W_;
            #pragma unroll
            for (int jx = 0; jx < 3; jx++)
                a += sc[jy*3 + jx] * vr[xs[jx]];
        }
        op[(size_t)d * P_] = f2tf(a * inv);
    }
}

// ---------------------------------------------------------------------------
extern "C" void kernel_launch(void* const* d_in, const int* in_sizes, int n_in,
                              void* d_out, int out_size)
{
    const float* x      = (const float*)d_in[0];
    const float* pos_w  = (const float*)d_in[1];
    const float* pos_b  = (const float*)d_in[2];
    const float* qkv_w  = (const float*)d_in[3];
    const float* proj_w = (const float*)d_in[4];
    float* out = (float*)d_out;

    float *gx, *gq, *go, *gwq, *gwp;
    cudaGetSymbolAddress((void**)&gx,  g_x);
    cudaGetSymbolAddress((void**)&gq,  g_qkv);
    cudaGetSymbolAddress((void**)&go,  g_xo);
    cudaGetSymbolAddress((void**)&gwq, g_wq);
    cudaGetSymbolAddress((void**)&gwp, g_wp);

    cudaFuncSetAttribute(gemm_mma, cudaFuncAttributeMaxDynamicSharedMemorySize, GEMM_DYN);
    cudaFuncSetAttribute(attn_kernel, cudaFuncAttributeMaxDynamicSharedMemorySize, ATT_SMEM);

    // Stage 0: weight prep (round + pair-permute)
    prep_w<<<(MQKV*C_ + 255)/256, 256>>>(qkv_w, proj_w);

    // Stage 1: positional dwconv + residual + bias
    {
        int total = B_*C_*P_;
        pos_kernel<<<(total + 255)/256, 256>>>(x, pos_w, pos_b);
    }
    // Stage 2: qkv 1x1 conv (576 x 192 x 16384 per batch)
    {
        dim3 grid(P_/GBN, MQKV/GBM, B_);
        gemm_mma<<<grid, 256, GEMM_DYN>>>(gwq, gx, gq, MQKV);
    }
    // Stage 3: attention (smem row-staged)
    {
        dim3 grid(H_, NH*ND, B_);
        attn_kernel<<<grid, 256, ATT_SMEM>>>();
    }
    // Stage 4: projection (192 x 192 x 16384 per batch)
    {
        dim3 grid(P_/GBN, C_/GBM, B_);
        gemm_mma<<<grid, 256, GEMM_DYN>>>(gwp, go, out, C_);
    }
}

// round 15
// speedup vs baseline: 1.4210x; 1.4210x over previous
#include <cuda_runtime.h>
#include <cstdint>
#include <cstddef>

// Problem constants
#define B_   4
#define C_   192
#define H_   128
#define W_   128
#define P_   16384
#define ND   3
#define C2   64
#define NH   2
#define HD   32
#define MQKV 576
#define SCALE 0.17677669529663687f   // 32^-0.5

// Scratch (alloc-free: __device__ globals)
__device__ float g_x  [(size_t)B_*C_*P_];     // tf32-rounded, qkv-gemm input
__device__ float g_qkv[(size_t)B_*MQKV*P_];   // fp32, attention input
__device__ float g_xo [(size_t)B_*C_*P_];     // tf32-rounded, proj-gemm input
__device__ float g_wq [(size_t)MQKV*C_];      // qkv_w: rounded + pair-permuted
__device__ float g_wp [(size_t)C_*C_];        // proj_w: rounded + pair-permuted

__device__ __forceinline__ float f2tf(float f) {
    uint32_t u;
    asm("cvt.rna.tf32.f32 %0, %1;" : "=r"(u) : "f"(f));
    return __uint_as_float(u);
}

// ---------------------------------------------------------------------------
// Stage 0: weight prep — round to tf32 and pair-permute (k,k+4) per kstep-of-8
// ---------------------------------------------------------------------------
__global__ __launch_bounds__(256) void prep_w(
    const float* __restrict__ qkv_w, const float* __restrict__ proj_w)
{
    int i = blockIdx.x * 256 + threadIdx.x;
    if (i < MQKV * C_) {
        int m = i / C_, k = i - m * C_;
        int dc = (k >> 3) * 8 + 2 * (k & 3) + ((k >> 2) & 1);
        g_wq[(size_t)m * C_ + dc] = f2tf(qkv_w[i]);
    }
    if (i < C_ * C_) {
        int m = i / C_, k = i - m * C_;
        int dc = (k >> 3) * 8 + 2 * (k & 3) + ((k >> 2) & 1);
        g_wp[(size_t)m * C_ + dc] = f2tf(proj_w[i]);
    }
}

// ---------------------------------------------------------------------------
// Stage 1: depthwise 3x3 conv (zero pad) + residual + bias; output tf32-rounded
// ---------------------------------------------------------------------------
__global__ __launch_bounds__(256) void pos_kernel(
    const float* __restrict__ x, const float* __restrict__ pw,
    const float* __restrict__ pb)
{
    int idx = blockIdx.x * 256 + threadIdx.x;
    if (idx >= B_*C_*P_) return;
    int pix = idx & (P_-1);
    int bc  = idx >> 14;
    int c   = bc % C_;
    int y  = pix >> 7;
    int xx = pix & 127;
    const float* xb = x + (size_t)bc * P_;
    const float* w  = pw + c * 9;
    float s = x[idx];
    #pragma unroll
    for (int kh = 0; kh < 3; kh++) {
        int yy = y + kh - 1;
        if (yy < 0 || yy >= H_) continue;
        #pragma unroll
        for (int kw = 0; kw < 3; kw++) {
            int xc = xx + kw - 1;
            if (xc < 0 || xc >= W_) continue;
            s += xb[yy * W_ + xc] * w[kh * 3 + kw];
        }
    }
    g_x[idx] = f2tf(s + pb[c]);
}

// ---------------------------------------------------------------------------
// tf32 mma.sync GEMM (pre-rounded inputs -> staging is pure copy, no cvt).
// CTA tile 96(m) x 128(n) x 16(k); double-buffered smem; 2 CTAs/SM.
// 8 warps (2m x 4n); warp tile 48x32 (mt=3) via m16n8k8 tf32 HMMA.
// B frags reused in regs across mt -> 22% fewer LDS issues per HMMA than mt=2.
// ---------------------------------------------------------------------------
#define GBM 96
#define GBN 128
#define GK  192
#define BKT 16
#define NKT 12
#define AP  24
#define BNP 136
#define AS_WORDS (GBM * AP)     // 2304
#define BS_WORDS (BKT * BNP)    // 2176

__device__ __forceinline__ void mma_tf32(float (&d)[4], const uint32_t (&a)[4],
                                         const uint32_t (&b)[2]) {
    asm volatile(
        "mma.sync.aligned.m16n8k8.row.col.f32.tf32.tf32.f32 "
        "{%0,%1,%2,%3}, {%4,%5,%6,%7}, {%8,%9}, {%0,%1,%2,%3};"
        : "+f"(d[0]), "+f"(d[1]), "+f"(d[2]), "+f"(d[3])
        : "r"(a[0]), "r"(a[1]), "r"(a[2]), "r"(a[3]), "r"(b[0]), "r"(b[1]));
}

__global__ __launch_bounds__(256, 2) void gemm_mma(
    const float* __restrict__ Wp, const float* __restrict__ X,
    float* __restrict__ Y, int Mtot)
{
    __shared__ float As[2][AS_WORDS];
    __shared__ float Bs[2][BS_WORDS];

    int tid  = threadIdx.x;
    int lane = tid & 31;
    int wid  = tid >> 5;
    int wm   = wid & 1;
    int wn   = wid >> 1;
    int n0   = blockIdx.x * GBN;
    int m0   = blockIdx.y * GBM;
    int b    = blockIdx.z;
    const float* Xb = X + (size_t)b * C_ * P_;
    float* Yb = Y + (size_t)b * Mtot * P_;

    int lr = lane >> 2;
    int lc = lane & 3;

    // A staging: 96 rows x 16 k = 384 float4s; thread does idx=tid and
    // (if tid<128) idx=tid+256. Pure copy of pre-rounded/permuted W.
    int ar0 = tid >> 2;
    int ac0 = (tid & 3) << 2;
    int ar1 = (tid + 256) >> 2;
    int ac1 = ac0;
    const float* aptr0 = Wp + (size_t)(m0 + ar0) * GK + ac0;
    const float* aptr1 = Wp + (size_t)(m0 + ar1) * GK + ac1;
    int as0 = ar0 * AP + ac0;
    int as1 = ar1 * AP + ac1;
    bool a1v = (tid < 128);
    // B staging: 2 float4/thread.
    int brow0 = tid >> 5;
    int brow1 = brow0 + 8;
    int bc4   = (tid & 31) << 2;
    const float* bptr0 = Xb + (size_t)brow0 * P_ + n0 + bc4;
    const float* bptr1 = Xb + (size_t)brow1 * P_ + n0 + bc4;
    int bs0 = brow0 * BNP + bc4;
    int bs1 = brow1 * BNP + bc4;

    float4 aw0, aw1, bw0, bw1;

    // prologue: tile 0 -> buf 0 (direct)
    aw0 = *reinterpret_cast<const float4*>(aptr0);
    if (a1v) aw1 = *reinterpret_cast<const float4*>(aptr1);
    bw0 = *reinterpret_cast<const float4*>(bptr0);
    bw1 = *reinterpret_cast<const float4*>(bptr1);
    *reinterpret_cast<float4*>(&As[0][as0]) = aw0;
    if (a1v) *reinterpret_cast<float4*>(&As[0][as1]) = aw1;
    *reinterpret_cast<float4*>(&Bs[0][bs0]) = bw0;
    *reinterpret_cast<float4*>(&Bs[0][bs1]) = bw1;
    __syncthreads();
    // prefetch tile 1
    aw0 = *reinterpret_cast<const float4*>(aptr0 + BKT);
    if (a1v) aw1 = *reinterpret_cast<const float4*>(aptr1 + BKT);
    bw0 = *reinterpret_cast<const float4*>(bptr0 + (size_t)BKT * P_);
    bw1 = *reinterpret_cast<const float4*>(bptr1 + (size_t)BKT * P_);

    float acc[3][4][4];
    #pragma unroll
    for (int mt = 0; mt < 3; mt++)
        #pragma unroll
        for (int nt = 0; nt < 4; nt++)
            #pragma unroll
            for (int r = 0; r < 4; r++) acc[mt][nt][r] = 0.f;

    for (int t = 0; t < NKT; t++) {
        const float* Asb = As[t & 1];
        const uint32_t* Bsu = reinterpret_cast<const uint32_t*>(Bs[t & 1]);

        #pragma unroll
        for (int s = 0; s < 2; s++) {
            uint32_t a[3][4], bf[4][2];
            #pragma unroll
            for (int mt = 0; mt < 3; mt++) {
                int r = wm * 48 + mt * 16 + lr;
                uint2 u0 = *reinterpret_cast<const uint2*>(Asb + r * AP + s * 8 + 2 * lc);
                uint2 u1 = *reinterpret_cast<const uint2*>(Asb + (r + 8) * AP + s * 8 + 2 * lc);
                a[mt][0] = u0.x; a[mt][2] = u0.y;
                a[mt][1] = u1.x; a[mt][3] = u1.y;
            }
            #pragma unroll
            for (int nt = 0; nt < 4; nt++) {
                int c0 = (s * 8 + lc) * BNP + wn * 32 + nt * 8 + lr;
                bf[nt][0] = Bsu[c0];
                bf[nt][1] = Bsu[c0 + 4 * BNP];
            }
            #pragma unroll
            for (int mt = 0; mt < 3; mt++)
                #pragma unroll
                for (int nt = 0; nt < 4; nt++)
                    mma_tf32(acc[mt][nt], a[mt], bf[nt]);
        }

        if (t + 1 < NKT) {
            *reinterpret_cast<float4*>(&As[(t + 1) & 1][as0]) = aw0;
            if (a1v) *reinterpret_cast<float4*>(&As[(t + 1) & 1][as1]) = aw1;
            *reinterpret_cast<float4*>(&Bs[(t + 1) & 1][bs0]) = bw0;
            *reinterpret_cast<float4*>(&Bs[(t + 1) & 1][bs1]) = bw1;
        }
        __syncthreads();
        if (t + 2 < NKT) {
            int k0 = (t + 2) * BKT;
            aw0 = *reinterpret_cast<const float4*>(aptr0 + k0);
            if (a1v) aw1 = *reinterpret_cast<const float4*>(aptr1 + k0);
            bw0 = *reinterpret_cast<const float4*>(bptr0 + (size_t)k0 * P_);
            bw1 = *reinterpret_cast<const float4*>(bptr1 + (size_t)k0 * P_);
        }
    }

    #pragma unroll
    for (int mt = 0; mt < 3; mt++)
        #pragma unroll
        for (int nt = 0; nt < 4; nt++) {
            int r = m0 + wm * 48 + mt * 16 + lr;
            int c = n0 + wn * 32 + nt * 8 + lc * 2;
            float2 v0 = { acc[mt][nt][0], acc[mt][nt][1] };
            float2 v1 = { acc[mt][nt][2], acc[mt][nt][3] };
            *reinterpret_cast<float2*>(Yb + (size_t)r * P_ + c)       = v0;
            *reinterpret_cast<float2*>(Yb + (size_t)(r + 8) * P_ + c) = v1;
        }
}

// ---------------------------------------------------------------------------
// Stage 3: attention via SMEM row-staging (R13, unchanged).
// ---------------------------------------------------------------------------
#define HHD 16
#define KV_WORDS (HD * 3 * W_)          // 12288 floats (48 KB)
#define ATT_SMEM ((KV_WORDS + 2 * W_ * 9) * 4)   // 58368 B

__device__ __forceinline__ int reflect_i(int t, int n) {
    return t < 0 ? -t : (t >= n ? 2*n - 2 - t : t);
}

__global__ __launch_bounds__(256) void attn_kernel()
{
    extern __shared__ float asm_[];
    float* kv  = asm_;                 // [32 ch][3 rows][128 x]
    float* ssc = asm_ + KV_WORDS;      // [2][128*9]

    int tid  = threadIdx.x;
    int half = tid >> 7;
    int px   = tid & 127;
    int y    = blockIdx.x;
    int head = blockIdx.y & 1;
    int dil  = blockIdx.y >> 1;
    int b    = blockIdx.z;
    int dl   = dil + 1;
    int p    = y * W_ + px;

    int xs[3];
    #pragma unroll
    for (int jx = 0; jx < 3; jx++)
        xs[jx] = reflect_i(px + (jx - 1) * dl, W_);
    int ys[3];
    #pragma unroll
    for (int jy = 0; jy < 3; jy++)
        ys[jy] = reflect_i(y + (jy - 1) * dl, H_);

    size_t chan0 = (size_t)b * MQKV + dil * C2 + head * HD;
    const float* qp = g_qkv + (chan0 + (size_t)half * HHD) * P_;
    const float* kp = g_qkv + (chan0 + (size_t)C_)   * P_;
    const float* vp = g_qkv + (chan0 + (size_t)2*C_) * P_;

    #pragma unroll
    for (int i = 0; i < 12; i++) {
        int u    = tid + i * 256;
        int pair = u >> 5;
        int x4   = (u & 31) << 2;
        int ch   = pair / 3;
        int jy   = pair - ch * 3;
        float4 v = *reinterpret_cast<const float4*>(
            kp + (size_t)ch * P_ + ys[jy] * W_ + x4);
        *reinterpret_cast<float4*>(kv + pair * W_ + x4) = v;
    }
    __syncthreads();

    float sc[9];
    #pragma unroll
    for (int j = 0; j < 9; j++) sc[j] = 0.f;

    #pragma unroll 4
    for (int d = 0; d < HHD; d++) {
        float qd = qp[(size_t)d * P_ + p];
        const float* kb = kv + (half * HHD + d) * 3 * W_;
        #pragma unroll
        for (int jy = 0; jy < 3; jy++) {
            const float* kr = kb + jy * W_;
            #pragma unroll
            for (int jx = 0; jx < 3; jx++)
                sc[jy*3 + jx] += qd * kr[xs[jx]];
        }
    }

    {
        float* mine = &ssc[half * (W_ * 9) + px * 9];
        #pragma unroll
        for (int j = 0; j < 9; j++) mine[j] = sc[j];
    }
    __syncthreads();
    {
        const float* other = &ssc[(half ^ 1) * (W_ * 9) + px * 9];
        #pragma unroll
        for (int j = 0; j < 9; j++) sc[j] += other[j];
    }

    float mx = sc[0] * SCALE;
    #pragma unroll
    for (int j = 0; j < 9; j++) { sc[j] *= SCALE; mx = fmaxf(mx, sc[j]); }
    float sum = 0.f;
    #pragma unroll
    for (int j = 0; j < 9; j++) { sc[j] = __expf(sc[j] - mx); sum += sc[j]; }
    float inv = 1.f / sum;

    #pragma unroll
    for (int i = 0; i < 12; i++) {
        int u    = tid + i * 256;
        int pair = u >> 5;
        int x4   = (u & 31) << 2;
        int ch   = pair / 3;
        int jy   = pair - ch * 3;
        float4 v = *reinterpret_cast<const float4*>(
            vp + (size_t)ch * P_ + ys[jy] * W_ + x4);
        *reinterpret_cast<float4*>(kv + pair * W_ + x4) = v;
    }
    __syncthreads();

    float* op = g_xo + ((size_t)b * C_ + dil * C2 + head * HD
                        + (size_t)half * HHD) * P_ + p;
    #pragma unroll 4
    for (int d = 0; d < HHD; d++) {
        const float* vb = kv + (half * HHD + d) * 3 * W_;
        float a = 0.f;
        #pragma unroll
        for (int jy = 0; jy < 3; jy++) {
            const float* vr = vb + jy * W_;
            #pragma unroll
            for (int jx = 0; jx < 3; jx++)
                a += sc[jy*3 + jx] * vr[xs[jx]];
        }
        op[(size_t)d * P_] = f2tf(a * inv);
    }
}

// ---------------------------------------------------------------------------
extern "C" void kernel_launch(void* const* d_in, const int* in_sizes, int n_in,
                              void* d_out, int out_size)
{
    const float* x      = (const float*)d_in[0];
    const float* pos_w  = (const float*)d_in[1];
    const float* pos_b  = (const float*)d_in[2];
    const float* qkv_w  = (const float*)d_in[3];
    const float* proj_w = (const float*)d_in[4];
    float* out = (float*)d_out;

    float *gx, *gq, *go, *gwq, *gwp;
    cudaGetSymbolAddress((void**)&gx,  g_x);
    cudaGetSymbolAddress((void**)&gq,  g_qkv);
    cudaGetSymbolAddress((void**)&go,  g_xo);
    cudaGetSymbolAddress((void**)&gwq, g_wq);
    cudaGetSymbolAddress((void**)&gwp, g_wp);

    cudaFuncSetAttribute(attn_kernel, cudaFuncAttributeMaxDynamicSharedMemorySize, ATT_SMEM);

    // Stage 0: weight prep (round + pair-permute)
    prep_w<<<(MQKV*C_ + 255)/256, 256>>>(qkv_w, proj_w);

    // Stage 1: positional dwconv + residual + bias
    {
        int total = B_*C_*P_;
        pos_kernel<<<(total + 255)/256, 256>>>(x, pos_w, pos_b);
    }
    // Stage 2: qkv 1x1 conv (576 x 192 x 16384 per batch; 6 m-tiles)
    {
        dim3 grid(P_/GBN, MQKV/GBM, B_);
        gemm_mma<<<grid, 256>>>(gwq, gx, gq, MQKV);
    }
    // Stage 3: attention (smem row-staged)
    {
        dim3 grid(H_, NH*ND, B_);
        attn_kernel<<<grid, 256, ATT_SMEM>>>();
    }
    // Stage 4: projection (192 x 192 x 16384 per batch; 2 m-tiles)
    {
        dim3 grid(P_/GBN, C_/GBM, B_);
        gemm_mma<<<grid, 256>>>(gwp, go, out, C_);
    }
}

// round 16
// speedup vs baseline: 1.4401x; 1.0135x over previous
#include <cuda_runtime.h>
#include <cstdint>
#include <cstddef>

// Problem constants
#define B_   4
#define C_   192
#define H_   128
#define W_   128
#define P_   16384
#define ND   3
#define C2   64
#define NH   2
#define HD   32
#define MQKV 576
#define SCALE 0.17677669529663687f   // 32^-0.5

// Scratch (alloc-free: __device__ globals)
__device__ float g_x  [(size_t)B_*C_*P_];     // tf32-rounded, qkv-gemm input
__device__ float g_qkv[(size_t)B_*MQKV*P_];   // fp32, attention input
__device__ float g_xo [(size_t)B_*C_*P_];     // tf32-rounded, proj-gemm input
__device__ float g_wq [(size_t)MQKV*C_];      // qkv_w: rounded + pair-permuted
__device__ float g_wp [(size_t)C_*C_];        // proj_w: rounded + pair-permuted

__device__ __forceinline__ float f2tf(float f) {
    uint32_t u;
    asm("cvt.rna.tf32.f32 %0, %1;" : "=r"(u) : "f"(f));
    return __uint_as_float(u);
}

// ---------------------------------------------------------------------------
// Stage 0: weight prep — round to tf32 and pair-permute (k,k+4) per kstep-of-8
// ---------------------------------------------------------------------------
__global__ __launch_bounds__(256) void prep_w(
    const float* __restrict__ qkv_w, const float* __restrict__ proj_w)
{
    int i = blockIdx.x * 256 + threadIdx.x;
    if (i < MQKV * C_) {
        int m = i / C_, k = i - m * C_;
        int dc = (k >> 3) * 8 + 2 * (k & 3) + ((k >> 2) & 1);
        g_wq[(size_t)m * C_ + dc] = f2tf(qkv_w[i]);
    }
    if (i < C_ * C_) {
        int m = i / C_, k = i - m * C_;
        int dc = (k >> 3) * 8 + 2 * (k & 3) + ((k >> 2) & 1);
        g_wp[(size_t)m * C_ + dc] = f2tf(proj_w[i]);
    }
}

// ---------------------------------------------------------------------------
// Stage 1: depthwise 3x3 conv (zero pad) + residual + bias, 4 px per thread.
// Loads per thread: 3 rows x (1 float4 + 2 edge scalars). Output tf32-rounded.
// Same kh->kw summation order as the scalar version (bitwise identical).
// ---------------------------------------------------------------------------
__global__ __launch_bounds__(256) void pos_kernel(
    const float* __restrict__ x, const float* __restrict__ pw,
    const float* __restrict__ pb)
{
    int idx4 = blockIdx.x * 256 + threadIdx.x;     // one per 4 pixels
    if (idx4 >= B_*C_*(P_/4)) return;
    int p4 = idx4 & (P_/4 - 1);
    int bc = idx4 >> 12;                           // P_/4 = 4096
    int c  = bc % C_;
    int y  = p4 >> 5;                              // 32 float4 per row
    int x0 = (p4 & 31) << 2;

    const float* xb = x + (size_t)bc * P_;
    const float* w  = pw + c * 9;

    // gather 3 rows of 6 values each (x0-1 .. x0+4), zero-padded
    float r[3][6];
    #pragma unroll
    for (int kh = 0; kh < 3; kh++) {
        int yy = y + kh - 1;
        if (yy < 0 || yy >= H_) {
            #pragma unroll
            for (int j = 0; j < 6; j++) r[kh][j] = 0.f;
        } else {
            const float* row = xb + yy * W_;
            float4 m4 = *reinterpret_cast<const float4*>(row + x0);
            r[kh][0] = (x0 > 0)       ? row[x0 - 1] : 0.f;
            r[kh][1] = m4.x; r[kh][2] = m4.y; r[kh][3] = m4.z; r[kh][4] = m4.w;
            r[kh][5] = (x0 + 4 < W_)  ? row[x0 + 4] : 0.f;
        }
    }

    float4 xc = *reinterpret_cast<const float4*>(xb + y * W_ + x0);
    float xin[4] = { xc.x, xc.y, xc.z, xc.w };
    float bias = pb[c];

    float4 outv;
    float* outa = &outv.x;
    #pragma unroll
    for (int j = 0; j < 4; j++) {
        float s = xin[j];
        #pragma unroll
        for (int kh = 0; kh < 3; kh++)
            #pragma unroll
            for (int kw = 0; kw < 3; kw++)
                s += r[kh][j + kw] * w[kh * 3 + kw];
        outa[j] = f2tf(s + bias);
    }
    *reinterpret_cast<float4*>(g_x + (size_t)bc * P_ + y * W_ + x0) = outv;
}

// ---------------------------------------------------------------------------
// tf32 mma.sync GEMM (pre-rounded inputs -> staging is pure copy, no cvt).
// CTA tile 96(m) x 128(n) x 16(k); double-buffered smem; 2 CTAs/SM.
// 8 warps (2m x 4n); warp tile 48x32 (mt=3) via m16n8k8 tf32 HMMA.
// ---------------------------------------------------------------------------
#define GBM 96
#define GBN 128
#define GK  192
#define BKT 16
#define NKT 12
#define AP  24
#define BNP 136
#define AS_WORDS (GBM * AP)     // 2304
#define BS_WORDS (BKT * BNP)    // 2176

__device__ __forceinline__ void mma_tf32(float (&d)[4], const uint32_t (&a)[4],
                                         const uint32_t (&b)[2]) {
    asm volatile(
        "mma.sync.aligned.m16n8k8.row.col.f32.tf32.tf32.f32 "
        "{%0,%1,%2,%3}, {%4,%5,%6,%7}, {%8,%9}, {%0,%1,%2,%3};"
        : "+f"(d[0]), "+f"(d[1]), "+f"(d[2]), "+f"(d[3])
        : "r"(a[0]), "r"(a[1]), "r"(a[2]), "r"(a[3]), "r"(b[0]), "r"(b[1]));
}

__global__ __launch_bounds__(256, 2) void gemm_mma(
    const float* __restrict__ Wp, const float* __restrict__ X,
    float* __restrict__ Y, int Mtot)
{
    __shared__ float As[2][AS_WORDS];
    __shared__ float Bs[2][BS_WORDS];

    int tid  = threadIdx.x;
    int lane = tid & 31;
    int wid  = tid >> 5;
    int wm   = wid & 1;
    int wn   = wid >> 1;
    int n0   = blockIdx.x * GBN;
    int m0   = blockIdx.y * GBM;
    int b    = blockIdx.z;
    const float* Xb = X + (size_t)b * C_ * P_;
    float* Yb = Y + (size_t)b * Mtot * P_;

    int lr = lane >> 2;
    int lc = lane & 3;

    int ar0 = tid >> 2;
    int ac0 = (tid & 3) << 2;
    int ar1 = (tid + 256) >> 2;
    const float* aptr0 = Wp + (size_t)(m0 + ar0) * GK + ac0;
    const float* aptr1 = Wp + (size_t)(m0 + ar1) * GK + ac0;
    int as0 = ar0 * AP + ac0;
    int as1 = ar1 * AP + ac0;
    bool a1v = (tid < 128);
    int brow0 = tid >> 5;
    int brow1 = brow0 + 8;
    int bc4   = (tid & 31) << 2;
    const float* bptr0 = Xb + (size_t)brow0 * P_ + n0 + bc4;
    const float* bptr1 = Xb + (size_t)brow1 * P_ + n0 + bc4;
    int bs0 = brow0 * BNP + bc4;
    int bs1 = brow1 * BNP + bc4;

    float4 aw0, aw1, bw0, bw1;

    aw0 = *reinterpret_cast<const float4*>(aptr0);
    if (a1v) aw1 = *reinterpret_cast<const float4*>(aptr1);
    bw0 = *reinterpret_cast<const float4*>(bptr0);
    bw1 = *reinterpret_cast<const float4*>(bptr1);
    *reinterpret_cast<float4*>(&As[0][as0]) = aw0;
    if (a1v) *reinterpret_cast<float4*>(&As[0][as1]) = aw1;
    *reinterpret_cast<float4*>(&Bs[0][bs0]) = bw0;
    *reinterpret_cast<float4*>(&Bs[0][bs1]) = bw1;
    __syncthreads();
    aw0 = *reinterpret_cast<const float4*>(aptr0 + BKT);
    if (a1v) aw1 = *reinterpret_cast<const float4*>(aptr1 + BKT);
    bw0 = *reinterpret_cast<const float4*>(bptr0 + (size_t)BKT * P_);
    bw1 = *reinterpret_cast<const float4*>(bptr1 + (size_t)BKT * P_);

    float acc[3][4][4];
    #pragma unroll
    for (int mt = 0; mt < 3; mt++)
        #pragma unroll
        for (int nt = 0; nt < 4; nt++)
            #pragma unroll
            for (int r = 0; r < 4; r++) acc[mt][nt][r] = 0.f;

    for (int t = 0; t < NKT; t++) {
        const float* Asb = As[t & 1];
        const uint32_t* Bsu = reinterpret_cast<const uint32_t*>(Bs[t & 1]);

        #pragma unroll
        for (int s = 0; s < 2; s++) {
            uint32_t a[3][4], bf[4][2];
            #pragma unroll
            for (int mt = 0; mt < 3; mt++) {
                int r = wm * 48 + mt * 16 + lr;
                uint2 u0 = *reinterpret_cast<const uint2*>(Asb + r * AP + s * 8 + 2 * lc);
                uint2 u1 = *reinterpret_cast<const uint2*>(Asb + (r + 8) * AP + s * 8 + 2 * lc);
                a[mt][0] = u0.x; a[mt][2] = u0.y;
                a[mt][1] = u1.x; a[mt][3] = u1.y;
            }
            #pragma unroll
            for (int nt = 0; nt < 4; nt++) {
                int c0 = (s * 8 + lc) * BNP + wn * 32 + nt * 8 + lr;
                bf[nt][0] = Bsu[c0];
                bf[nt][1] = Bsu[c0 + 4 * BNP];
            }
            #pragma unroll
            for (int mt = 0; mt < 3; mt++)
                #pragma unroll
                for (int nt = 0; nt < 4; nt++)
                    mma_tf32(acc[mt][nt], a[mt], bf[nt]);
        }

        if (t + 1 < NKT) {
            *reinterpret_cast<float4*>(&As[(t + 1) & 1][as0]) = aw0;
            if (a1v) *reinterpret_cast<float4*>(&As[(t + 1) & 1][as1]) = aw1;
            *reinterpret_cast<float4*>(&Bs[(t + 1) & 1][bs0]) = bw0;
            *reinterpret_cast<float4*>(&Bs[(t + 1) & 1][bs1]) = bw1;
        }
        __syncthreads();
        if (t + 2 < NKT) {
            int k0 = (t + 2) * BKT;
            aw0 = *reinterpret_cast<const float4*>(aptr0 + k0);
            if (a1v) aw1 = *reinterpret_cast<const float4*>(aptr1 + k0);
            bw0 = *reinterpret_cast<const float4*>(bptr0 + (size_t)k0 * P_);
            bw1 = *reinterpret_cast<const float4*>(bptr1 + (size_t)k0 * P_);
        }
    }

    #pragma unroll
    for (int mt = 0; mt < 3; mt++)
        #pragma unroll
        for (int nt = 0; nt < 4; nt++) {
            int r = m0 + wm * 48 + mt * 16 + lr;
            int c = n0 + wn * 32 + nt * 8 + lc * 2;
            float2 v0 = { acc[mt][nt][0], acc[mt][nt][1] };
            float2 v1 = { acc[mt][nt][2], acc[mt][nt][3] };
            *reinterpret_cast<float2*>(Yb + (size_t)r * P_ + c)       = v0;
            *reinterpret_cast<float2*>(Yb + (size_t)(r + 8) * P_ + c) = v1;
        }
}

// ---------------------------------------------------------------------------
// Stage 3: attention via SMEM row-staging, shuffle-based score exchange.
// Compute mapping: half = tid&1, px = tid>>1 -> both halves of a pixel are
// adjacent lanes; partial-score exchange = one shfl.xor per score.
// smem = 48 KB (K/V tile only) -> 4 CTAs/SM.
// ---------------------------------------------------------------------------
#define HHD 16
#define KV_WORDS (HD * 3 * W_)          // 12288 floats (48 KB)
#define ATT_SMEM (KV_WORDS * 4)         // 49152 B

__device__ __forceinline__ int reflect_i(int t, int n) {
    return t < 0 ? -t : (t >= n ? 2*n - 2 - t : t);
}

__global__ __launch_bounds__(256, 4) void attn_kernel()
{
    extern __shared__ float asm_[];
    float* kv = asm_;                  // [32 ch][3 rows][128 x]

    int tid  = threadIdx.x;
    int half = tid & 1;
    int px   = tid >> 1;               // 0..127
    int y    = blockIdx.x;
    int head = blockIdx.y & 1;
    int dil  = blockIdx.y >> 1;
    int b    = blockIdx.z;
    int dl   = dil + 1;
    int p    = y * W_ + px;

    int xs[3];
    #pragma unroll
    for (int jx = 0; jx < 3; jx++)
        xs[jx] = reflect_i(px + (jx - 1) * dl, W_);
    int ys[3];
    #pragma unroll
    for (int jy = 0; jy < 3; jy++)
        ys[jy] = reflect_i(y + (jy - 1) * dl, H_);

    size_t chan0 = (size_t)b * MQKV + dil * C2 + head * HD;
    const float* qp = g_qkv + (chan0 + (size_t)half * HHD) * P_;
    const float* kp = g_qkv + (chan0 + (size_t)C_)   * P_;
    const float* vp = g_qkv + (chan0 + (size_t)2*C_) * P_;

    // --- Stage K (staging mapping uses raw tid; independent of compute map) ---
    #pragma unroll
    for (int i = 0; i < 12; i++) {
        int u    = tid + i * 256;
        int pair = u >> 5;
        int x4   = (u & 31) << 2;
        int ch   = pair / 3;
        int jy   = pair - ch * 3;
        float4 v = *reinterpret_cast<const float4*>(
            kp + (size_t)ch * P_ + ys[jy] * W_ + x4);
        *reinterpret_cast<float4*>(kv + pair * W_ + x4) = v;
    }
    __syncthreads();

    // --- Scores from smem (this half's 16 channels) ---
    float sc[9];
    #pragma unroll
    for (int j = 0; j < 9; j++) sc[j] = 0.f;

    #pragma unroll 4
    for (int d = 0; d < HHD; d++) {
        float qd = qp[(size_t)d * P_ + p];
        const float* kb = kv + (half * HHD + d) * 3 * W_;
        #pragma unroll
        for (int jy = 0; jy < 3; jy++) {
            const float* kr = kb + jy * W_;
            #pragma unroll
            for (int jx = 0; jx < 3; jx++)
                sc[jy*3 + jx] += qd * kr[xs[jx]];
        }
    }

    // exchange partial scores with the other half (adjacent lane)
    #pragma unroll
    for (int j = 0; j < 9; j++)
        sc[j] += __shfl_xor_sync(0xFFFFFFFFu, sc[j], 1);

    // softmax over 9 (redundant per half)
    float mx = sc[0] * SCALE;
    #pragma unroll
    for (int j = 0; j < 9; j++) { sc[j] *= SCALE; mx = fmaxf(mx, sc[j]); }
    float sum = 0.f;
    #pragma unroll
    for (int j = 0; j < 9; j++) { sc[j] = __expf(sc[j] - mx); sum += sc[j]; }
    float inv = 1.f / sum;

    __syncthreads();   // all K reads complete before V overwrites kv

    // --- Stage V into the same buffer ---
    #pragma unroll
    for (int i = 0; i < 12; i++) {
        int u    = tid + i * 256;
        int pair = u >> 5;
        int x4   = (u & 31) << 2;
        int ch   = pair / 3;
        int jy   = pair - ch * 3;
        float4 v = *reinterpret_cast<const float4*>(
            vp + (size_t)ch * P_ + ys[jy] * W_ + x4);
        *reinterpret_cast<float4*>(kv + pair * W_ + x4) = v;
    }
    __syncthreads();

    // --- Output pass (this half's 16 channels) ---
    float* op = g_xo + ((size_t)b * C_ + dil * C2 + head * HD
                        + (size_t)half * HHD) * P_ + p;
    #pragma unroll 4
    for (int d = 0; d < HHD; d++) {
        const float* vb = kv + (half * HHD + d) * 3 * W_;
        float a = 0.f;
        #pragma unroll
        for (int jy = 0; jy < 3; jy++) {
            const float* vr = vb + jy * W_;
            #pragma unroll
            for (int jx = 0; jx < 3; jx++)
                a += sc[jy*3 + jx] * vr[xs[jx]];
        }
        op[(size_t)d * P_] = f2tf(a * inv);
    }
}

// ---------------------------------------------------------------------------
extern "C" void kernel_launch(void* const* d_in, const int* in_sizes, int n_in,
                              void* d_out, int out_size)
{
    const float* x      = (const float*)d_in[0];
    const float* pos_w  = (const float*)d_in[1];
    const float* pos_b  = (const float*)d_in[2];
    const float* qkv_w  = (const float*)d_in[3];
    const float* proj_w = (const float*)d_in[4];
    float* out = (float*)d_out;

    float *gx, *gq, *go, *gwq, *gwp;
    cudaGetSymbolAddress((void**)&gx,  g_x);
    cudaGetSymbolAddress((void**)&gq,  g_qkv);
    cudaGetSymbolAddress((void**)&go,  g_xo);
    cudaGetSymbolAddress((void**)&gwq, g_wq);
    cudaGetSymbolAddress((void**)&gwp, g_wp);

    cudaFuncSetAttribute(attn_kernel, cudaFuncAttributeMaxDynamicSharedMemorySize, ATT_SMEM);

    // Stage 0: weight prep (round + pair-permute)
    prep_w<<<(MQKV*C_ + 255)/256, 256>>>(qkv_w, proj_w);

    // Stage 1: positional dwconv + residual + bias (4 px / thread)
    {
        int total4 = B_*C_*(P_/4);
        pos_kernel<<<(total4 + 255)/256, 256>>>(x, pos_w, pos_b);
    }
    // Stage 2: qkv 1x1 conv (576 x 192 x 16384 per batch; 6 m-tiles)
    {
        dim3 grid(P_/GBN, MQKV/GBM, B_);
        gemm_mma<<<grid, 256>>>(gwq, gx, gq, MQKV);
    }
    // Stage 3: attention (smem row-staged, shfl exchange)
    {
        dim3 grid(H_, NH*ND, B_);
        attn_kernel<<<grid, 256, ATT_SMEM>>>();
    }
    // Stage 4: projection (192 x 192 x 16384 per batch; 2 m-tiles)
    {
        dim3 grid(P_/GBN, C_/GBM, B_);
        gemm_mma<<<grid, 256>>>(gwp, go, out, C_);
    }
}

// round 17
// speedup vs baseline: 1.5043x; 1.0445x over previous
#include <cuda_runtime.h>
#include <cstdint>
#include <cstddef>

// Problem constants
#define B_   4
#define C_   192
#define H_   128
#define W_   128
#define P_   16384
#define ND   3
#define C2   64
#define NH   2
#define HD   32
#define MQKV 576
#define SCALE 0.17677669529663687f   // 32^-0.5

// Scratch (alloc-free: __device__ globals)
__device__ float g_x  [(size_t)B_*C_*P_];     // tf32-rounded, qkv-gemm input
__device__ float g_qkv[(size_t)B_*MQKV*P_];   // fp32, attention input
__device__ float g_xo [(size_t)B_*C_*P_];     // tf32-rounded, proj-gemm input
__device__ float g_wq [(size_t)MQKV*C_];      // qkv_w: rounded + pair-permuted
__device__ float g_wp [(size_t)C_*C_];        // proj_w: rounded + pair-permuted

__device__ __forceinline__ float f2tf(float f) {
    uint32_t u;
    asm("cvt.rna.tf32.f32 %0, %1;" : "=r"(u) : "f"(f));
    return __uint_as_float(u);
}

// ---------------------------------------------------------------------------
// Stage 0: weight prep — round to tf32 and pair-permute (k,k+4) per kstep-of-8
// ---------------------------------------------------------------------------
__global__ __launch_bounds__(256) void prep_w(
    const float* __restrict__ qkv_w, const float* __restrict__ proj_w)
{
    int i = blockIdx.x * 256 + threadIdx.x;
    if (i < MQKV * C_) {
        int m = i / C_, k = i - m * C_;
        int dc = (k >> 3) * 8 + 2 * (k & 3) + ((k >> 2) & 1);
        g_wq[(size_t)m * C_ + dc] = f2tf(qkv_w[i]);
    }
    if (i < C_ * C_) {
        int m = i / C_, k = i - m * C_;
        int dc = (k >> 3) * 8 + 2 * (k & 3) + ((k >> 2) & 1);
        g_wp[(size_t)m * C_ + dc] = f2tf(proj_w[i]);
    }
}

// ---------------------------------------------------------------------------
// Stage 1: depthwise 3x3 conv + residual + bias, 4 px/thread (R16, kept).
// ---------------------------------------------------------------------------
__global__ __launch_bounds__(256) void pos_kernel(
    const float* __restrict__ x, const float* __restrict__ pw,
    const float* __restrict__ pb)
{
    int idx4 = blockIdx.x * 256 + threadIdx.x;
    if (idx4 >= B_*C_*(P_/4)) return;
    int p4 = idx4 & (P_/4 - 1);
    int bc = idx4 >> 12;
    int c  = bc % C_;
    int y  = p4 >> 5;
    int x0 = (p4 & 31) << 2;

    const float* xb = x + (size_t)bc * P_;
    const float* w  = pw + c * 9;

    float r[3][6];
    #pragma unroll
    for (int kh = 0; kh < 3; kh++) {
        int yy = y + kh - 1;
        if (yy < 0 || yy >= H_) {
            #pragma unroll
            for (int j = 0; j < 6; j++) r[kh][j] = 0.f;
        } else {
            const float* row = xb + yy * W_;
            float4 m4 = *reinterpret_cast<const float4*>(row + x0);
            r[kh][0] = (x0 > 0)      ? row[x0 - 1] : 0.f;
            r[kh][1] = m4.x; r[kh][2] = m4.y; r[kh][3] = m4.z; r[kh][4] = m4.w;
            r[kh][5] = (x0 + 4 < W_) ? row[x0 + 4] : 0.f;
        }
    }

    float4 xc = *reinterpret_cast<const float4*>(xb + y * W_ + x0);
    float xin[4] = { xc.x, xc.y, xc.z, xc.w };
    float bias = pb[c];

    float4 outv;
    float* outa = &outv.x;
    #pragma unroll
    for (int j = 0; j < 4; j++) {
        float s = xin[j];
        #pragma unroll
        for (int kh = 0; kh < 3; kh++)
            #pragma unroll
            for (int kw = 0; kw < 3; kw++)
                s += r[kh][j + kw] * w[kh * 3 + kw];
        outa[j] = f2tf(s + bias);
    }
    *reinterpret_cast<float4*>(g_x + (size_t)bc * P_ + y * W_ + x0) = outv;
}

// ---------------------------------------------------------------------------
// tf32 mma.sync GEMM. CTA 96x128x16, 8 warps (2m x 4n), warp tile 48x32.
// NEW: Bs columns permuted col' = (c&7)*16 + (c>>3) so each kstep's 4 B
// fragments load as 2 conflict-free LDS.128 (was 8 LDS.32).
// Per-kstep LDS issues: 6 LDS.64 (A) + 2 LDS.128 (B) for 12 HMMA.
// ---------------------------------------------------------------------------
#define GBM 96
#define GBN 128
#define GK  192
#define BKT 16
#define NKT 12
#define AP  24
#define BNP2 132
#define AS_WORDS (GBM * AP)      // 2304
#define BS_WORDS (BKT * BNP2)    // 2112

__device__ __forceinline__ void mma_tf32(float (&d)[4], const uint32_t (&a)[4],
                                         const uint32_t (&b)[2]) {
    asm volatile(
        "mma.sync.aligned.m16n8k8.row.col.f32.tf32.tf32.f32 "
        "{%0,%1,%2,%3}, {%4,%5,%6,%7}, {%8,%9}, {%0,%1,%2,%3};"
        : "+f"(d[0]), "+f"(d[1]), "+f"(d[2]), "+f"(d[3])
        : "r"(a[0]), "r"(a[1]), "r"(a[2]), "r"(a[3]), "r"(b[0]), "r"(b[1]));
}

__global__ __launch_bounds__(256, 2) void gemm_mma(
    const float* __restrict__ Wp, const float* __restrict__ X,
    float* __restrict__ Y, int Mtot)
{
    __shared__ float As[2][AS_WORDS];
    __shared__ float Bs[2][BS_WORDS];

    int tid  = threadIdx.x;
    int lane = tid & 31;
    int wid  = tid >> 5;
    int wm   = wid & 1;
    int wn   = wid >> 1;
    int n0   = blockIdx.x * GBN;
    int m0   = blockIdx.y * GBM;
    int b    = blockIdx.z;
    const float* Xb = X + (size_t)b * C_ * P_;
    float* Yb = Y + (size_t)b * Mtot * P_;

    int lr = lane >> 2;
    int lc = lane & 3;

    // A staging (unchanged): 384 float4s; thread does idx=tid (+256 if tid<128)
    int ar0 = tid >> 2;
    int ac0 = (tid & 3) << 2;
    int ar1 = (tid + 256) >> 2;
    const float* aptr0 = Wp + (size_t)(m0 + ar0) * GK + ac0;
    const float* aptr1 = Wp + (size_t)(m0 + ar1) * GK + ac0;
    int as0 = ar0 * AP + ac0;
    int as1 = ar1 * AP + ac0;
    bool a1v = (tid < 128);
    // B staging: 2 float4 loads/thread; writes 4 permuted scalars each.
    int brow0 = tid >> 5;
    int brow1 = brow0 + 8;
    int bc4   = (tid & 31) << 2;
    const float* bptr0 = Xb + (size_t)brow0 * P_ + n0 + bc4;
    const float* bptr1 = Xb + (size_t)brow1 * P_ + n0 + bc4;
    // col' base for this thread's 4 columns: ((bc4&7)+j)*16 + (bc4>>3)
    int colp = (bc4 & 7) * 16 + (bc4 >> 3);
    int bs0 = brow0 * BNP2 + colp;
    int bs1 = brow1 * BNP2 + colp;

    float4 aw0, aw1, bw0, bw1;

    // prologue: tile 0 -> buf 0
    aw0 = *reinterpret_cast<const float4*>(aptr0);
    if (a1v) aw1 = *reinterpret_cast<const float4*>(aptr1);
    bw0 = *reinterpret_cast<const float4*>(bptr0);
    bw1 = *reinterpret_cast<const float4*>(bptr1);
    *reinterpret_cast<float4*>(&As[0][as0]) = aw0;
    if (a1v) *reinterpret_cast<float4*>(&As[0][as1]) = aw1;
    Bs[0][bs0]      = bw0.x; Bs[0][bs0 + 16] = bw0.y;
    Bs[0][bs0 + 32] = bw0.z; Bs[0][bs0 + 48] = bw0.w;
    Bs[0][bs1]      = bw1.x; Bs[0][bs1 + 16] = bw1.y;
    Bs[0][bs1 + 32] = bw1.z; Bs[0][bs1 + 48] = bw1.w;
    __syncthreads();
    aw0 = *reinterpret_cast<const float4*>(aptr0 + BKT);
    if (a1v) aw1 = *reinterpret_cast<const float4*>(aptr1 + BKT);
    bw0 = *reinterpret_cast<const float4*>(bptr0 + (size_t)BKT * P_);
    bw1 = *reinterpret_cast<const float4*>(bptr1 + (size_t)BKT * P_);

    float acc[3][4][4];
    #pragma unroll
    for (int mt = 0; mt < 3; mt++)
        #pragma unroll
        for (int nt = 0; nt < 4; nt++)
            #pragma unroll
            for (int r = 0; r < 4; r++) acc[mt][nt][r] = 0.f;

    for (int t = 0; t < NKT; t++) {
        const float* Asb = As[t & 1];
        const float* Bsb = Bs[t & 1];

        #pragma unroll
        for (int s = 0; s < 2; s++) {
            uint32_t a[3][4], bf[4][2];
            #pragma unroll
            for (int mt = 0; mt < 3; mt++) {
                int r = wm * 48 + mt * 16 + lr;
                uint2 u0 = *reinterpret_cast<const uint2*>(Asb + r * AP + s * 8 + 2 * lc);
                uint2 u1 = *reinterpret_cast<const uint2*>(Asb + (r + 8) * AP + s * 8 + 2 * lc);
                a[mt][0] = u0.x; a[mt][2] = u0.y;
                a[mt][1] = u1.x; a[mt][3] = u1.y;
            }
            {
                int c0 = (s * 8 + lc) * BNP2 + lr * 16 + wn * 4;
                uint4 q0 = *reinterpret_cast<const uint4*>(Bsb + c0);
                uint4 q1 = *reinterpret_cast<const uint4*>(Bsb + c0 + 4 * BNP2);
                bf[0][0] = q0.x; bf[1][0] = q0.y; bf[2][0] = q0.z; bf[3][0] = q0.w;
                bf[0][1] = q1.x; bf[1][1] = q1.y; bf[2][1] = q1.z; bf[3][1] = q1.w;
            }
            #pragma unroll
            for (int mt = 0; mt < 3; mt++)
                #pragma unroll
                for (int nt = 0; nt < 4; nt++)
                    mma_tf32(acc[mt][nt], a[mt], bf[nt]);
        }

        if (t + 1 < NKT) {
            float* Asn = As[(t + 1) & 1];
            float* Bsn = Bs[(t + 1) & 1];
            *reinterpret_cast<float4*>(&Asn[as0]) = aw0;
            if (a1v) *reinterpret_cast<float4*>(&Asn[as1]) = aw1;
            Bsn[bs0]      = bw0.x; Bsn[bs0 + 16] = bw0.y;
            Bsn[bs0 + 32] = bw0.z; Bsn[bs0 + 48] = bw0.w;
            Bsn[bs1]      = bw1.x; Bsn[bs1 + 16] = bw1.y;
            Bsn[bs1 + 32] = bw1.z; Bsn[bs1 + 48] = bw1.w;
        }
        __syncthreads();
        if (t + 2 < NKT) {
            int k0 = (t + 2) * BKT;
            aw0 = *reinterpret_cast<const float4*>(aptr0 + k0);
            if (a1v) aw1 = *reinterpret_cast<const float4*>(aptr1 + k0);
            bw0 = *reinterpret_cast<const float4*>(bptr0 + (size_t)k0 * P_);
            bw1 = *reinterpret_cast<const float4*>(bptr1 + (size_t)k0 * P_);
        }
    }

    #pragma unroll
    for (int mt = 0; mt < 3; mt++)
        #pragma unroll
        for (int nt = 0; nt < 4; nt++) {
            int r = m0 + wm * 48 + mt * 16 + lr;
            int c = n0 + wn * 32 + nt * 8 + lc * 2;
            float2 v0 = { acc[mt][nt][0], acc[mt][nt][1] };
            float2 v1 = { acc[mt][nt][2], acc[mt][nt][3] };
            *reinterpret_cast<float2*>(Yb + (size_t)r * P_ + c)       = v0;
            *reinterpret_cast<float2*>(Yb + (size_t)(r + 8) * P_ + c) = v1;
        }
}

// ---------------------------------------------------------------------------
// Stage 3: attention via SMEM row-staging (R13 mapping restored:
// half = tid>>7 -> full-warp coalesced q loads / output stores; smem exchange).
// ---------------------------------------------------------------------------
#define HHD 16
#define KV_WORDS (HD * 3 * W_)          // 12288 floats (48 KB)
#define ATT_SMEM ((KV_WORDS + 2 * W_ * 9) * 4)   // 58368 B

__device__ __forceinline__ int reflect_i(int t, int n) {
    return t < 0 ? -t : (t >= n ? 2*n - 2 - t : t);
}

__global__ __launch_bounds__(256) void attn_kernel()
{
    extern __shared__ float asm_[];
    float* kv  = asm_;                 // [32 ch][3 rows][128 x]
    float* ssc = asm_ + KV_WORDS;      // [2][128*9]

    int tid  = threadIdx.x;
    int half = tid >> 7;
    int px   = tid & 127;
    int y    = blockIdx.x;
    int head = blockIdx.y & 1;
    int dil  = blockIdx.y >> 1;
    int b    = blockIdx.z;
    int dl   = dil + 1;
    int p    = y * W_ + px;

    int xs[3];
    #pragma unroll
    for (int jx = 0; jx < 3; jx++)
        xs[jx] = reflect_i(px + (jx - 1) * dl, W_);
    int ys[3];
    #pragma unroll
    for (int jy = 0; jy < 3; jy++)
        ys[jy] = reflect_i(y + (jy - 1) * dl, H_);

    size_t chan0 = (size_t)b * MQKV + dil * C2 + head * HD;
    const float* qp = g_qkv + (chan0 + (size_t)half * HHD) * P_;
    const float* kp = g_qkv + (chan0 + (size_t)C_)   * P_;
    const float* vp = g_qkv + (chan0 + (size_t)2*C_) * P_;

    #pragma unroll
    for (int i = 0; i < 12; i++) {
        int u    = tid + i * 256;
        int pair = u >> 5;
        int x4   = (u & 31) << 2;
        int ch   = pair / 3;
        int jy   = pair - ch * 3;
        float4 v = *reinterpret_cast<const float4*>(
            kp + (size_t)ch * P_ + ys[jy] * W_ + x4);
        *reinterpret_cast<float4*>(kv + pair * W_ + x4) = v;
    }
    __syncthreads();

    float sc[9];
    #pragma unroll
    for (int j = 0; j < 9; j++) sc[j] = 0.f;

    #pragma unroll 4
    for (int d = 0; d < HHD; d++) {
        float qd = qp[(size_t)d * P_ + p];
        const float* kb = kv + (half * HHD + d) * 3 * W_;
        #pragma unroll
        for (int jy = 0; jy < 3; jy++) {
            const float* kr = kb + jy * W_;
            #pragma unroll
            for (int jx = 0; jx < 3; jx++)
                sc[jy*3 + jx] += qd * kr[xs[jx]];
        }
    }

    {
        float* mine = &ssc[half * (W_ * 9) + px * 9];
        #pragma unroll
        for (int j = 0; j < 9; j++) mine[j] = sc[j];
    }
    __syncthreads();
    {
        const float* other = &ssc[(half ^ 1) * (W_ * 9) + px * 9];
        #pragma unroll
        for (int j = 0; j < 9; j++) sc[j] += other[j];
    }

    float mx = sc[0] * SCALE;
    #pragma unroll
    for (int j = 0; j < 9; j++) { sc[j] *= SCALE; mx = fmaxf(mx, sc[j]); }
    float sum = 0.f;
    #pragma unroll
    for (int j = 0; j < 9; j++) { sc[j] = __expf(sc[j] - mx); sum += sc[j]; }
    float inv = 1.f / sum;

    #pragma unroll
    for (int i = 0; i < 12; i++) {
        int u    = tid + i * 256;
        int pair = u >> 5;
        int x4   = (u & 31) << 2;
        int ch   = pair / 3;
        int jy   = pair - ch * 3;
        float4 v = *reinterpret_cast<const float4*>(
            vp + (size_t)ch * P_ + ys[jy] * W_ + x4);
        *reinterpret_cast<float4*>(kv + pair * W_ + x4) = v;
    }
    __syncthreads();

    float* op = g_xo + ((size_t)b * C_ + dil * C2 + head * HD
                        + (size_t)half * HHD) * P_ + p;
    #pragma unroll 4
    for (int d = 0; d < HHD; d++) {
        const float* vb = kv + (half * HHD + d) * 3 * W_;
        float a = 0.f;
        #pragma unroll
        for (int jy = 0; jy < 3; jy++) {
            const float* vr = vb + jy * W_;
            #pragma unroll
            for (int jx = 0; jx < 3; jx++)
                a += sc[jy*3 + jx] * vr[xs[jx]];
        }
        op[(size_t)d * P_] = f2tf(a * inv);
    }
}

// ---------------------------------------------------------------------------
extern "C" void kernel_launch(void* const* d_in, const int* in_sizes, int n_in,
                              void* d_out, int out_size)
{
    const float* x      = (const float*)d_in[0];
    const float* pos_w  = (const float*)d_in[1];
    const float* pos_b  = (const float*)d_in[2];
    const float* qkv_w  = (const float*)d_in[3];
    const float* proj_w = (const float*)d_in[4];
    float* out = (float*)d_out;

    float *gx, *gq, *go, *gwq, *gwp;
    cudaGetSymbolAddress((void**)&gx,  g_x);
    cudaGetSymbolAddress((void**)&gq,  g_qkv);
    cudaGetSymbolAddress((void**)&go,  g_xo);
    cudaGetSymbolAddress((void**)&gwq, g_wq);
    cudaGetSymbolAddress((void**)&gwp, g_wp);

    cudaFuncSetAttribute(attn_kernel, cudaFuncAttributeMaxDynamicSharedMemorySize, ATT_SMEM);

    // Stage 0: weight prep (round + pair-permute)
    prep_w<<<(MQKV*C_ + 255)/256, 256>>>(qkv_w, proj_w);

    // Stage 1: positional dwconv + residual + bias (4 px / thread)
    {
        int total4 = B_*C_*(P_/4);
        pos_kernel<<<(total4 + 255)/256, 256>>>(x, pos_w, pos_b);
    }
    // Stage 2: qkv 1x1 conv (576 x 192 x 16384 per batch; 6 m-tiles)
    {
        dim3 grid(P_/GBN, MQKV/GBM, B_);
        gemm_mma<<<grid, 256>>>(gwq, gx, gq, MQKV);
    }
    // Stage 3: attention (smem row-staged, R13 mapping)
    {
        dim3 grid(H_, NH*ND, B_);
        attn_kernel<<<grid, 256, ATT_SMEM>>>();
    }
    // Stage 4: projection (192 x 192 x 16384 per batch; 2 m-tiles)
    {
        dim3 grid(P_/GBN, C_/GBM, B_);
        gemm_mma<<<grid, 256>>>(gwp, go, out, C_);
    }
}